// round 15
// baseline (speedup 1.0000x reference)
#include <cuda_runtime.h>

// Problem dims (fixed by reference)
#define B 16
#define S 4096
#define D 1024      // D_IN = H = D_OUT = 1024
#define NCHUNK 64
#define SCHUNK (S / NCHUNK)   // 64
#define KSPLIT 4
#define KCHUNK (D / KSPLIT)   // 256
#define R_GRID 512            // K1 blocks; each handles 2 of the 1024 tasks

// Scratch (no device allocs allowed)
__device__ float g_part[B * NCHUNK * D];       // 4 MB
__device__ float g_m[B * D];
__device__ float g_enc[B * D];
__device__ unsigned g_flag[B * NCHUNK];        // monotonic task flags (+1/launch)

// ---------------------------------------------------------------------------
// K1: partial sums over S-chunks + in-kernel combine via flag handoff.
// grid R_GRID, block 256, 2 tasks per block.
//  - blocks 0..63 bias-init enc/out at entry (independent of everything).
//  - every task: coalesced part store, __threadfence, flag++ (monotonic).
//  - blocks 0..15: after their own tasks, spin until row b's 64 flags reach
//    this launch's generation (derived from their own t=0 increment), then
//    combine the 64 partials -> m[b]. All 512 blocks are co-resident
//    (512 < 148*8), so the spin cannot deadlock.
__global__ void __launch_bounds__(256)
reduce_combine_kernel(const float* __restrict__ x,
                      float* __restrict__ part,
                      float* __restrict__ m,
                      const float* __restrict__ b_enc,
                      float* __restrict__ enc,
                      const float* __restrict__ b_out,
                      float* __restrict__ out) {
    const int tid = threadIdx.x;  // 0..255
    const int bid = blockIdx.x;

    // Early bias init (blocks 0..63 cover all 16384 elements).
    if (bid < 64) {
        const int i = bid * 256 + tid;
        const int d = i & (D - 1);
        enc[i] = b_enc[d];
        out[i] = b_out[d];
    }

    unsigned gen = 0;

    #pragma unroll
    for (int t = 0; t < 2; t++) {
        const int task = bid + t * R_GRID;   // 0..1023
        const int b = task >> 6;             // task / NCHUNK
        const int chunk = task & (NCHUNK - 1);

        const float4* xb = (const float4*)(x + (size_t)b * S * D
                                             + (size_t)chunk * SCHUNK * D);

        float4 acc0 = make_float4(0.f, 0.f, 0.f, 0.f);
        float4 acc1 = make_float4(0.f, 0.f, 0.f, 0.f);
        float4 acc2 = make_float4(0.f, 0.f, 0.f, 0.f);
        float4 acc3 = make_float4(0.f, 0.f, 0.f, 0.f);

        #pragma unroll 2
        for (int s = 0; s < SCHUNK; s += 8) {
            float4 v[8];
            #pragma unroll
            for (int j = 0; j < 8; j++)
                v[j] = __ldcs(&xb[(size_t)(s + j) * (D / 4) + tid]);
            #pragma unroll
            for (int j = 0; j < 8; j += 4) {
                acc0.x += v[j].x;   acc0.y += v[j].y;   acc0.z += v[j].z;   acc0.w += v[j].w;
                acc1.x += v[j+1].x; acc1.y += v[j+1].y; acc1.z += v[j+1].z; acc1.w += v[j+1].w;
                acc2.x += v[j+2].x; acc2.y += v[j+2].y; acc2.z += v[j+2].z; acc2.w += v[j+2].w;
                acc3.x += v[j+3].x; acc3.y += v[j+3].y; acc3.z += v[j+3].z; acc3.w += v[j+3].w;
            }
        }

        float4 acc;
        acc.x = (acc0.x + acc1.x) + (acc2.x + acc3.x);
        acc.y = (acc0.y + acc1.y) + (acc2.y + acc3.y);
        acc.z = (acc0.z + acc1.z) + (acc2.z + acc3.z);
        acc.w = (acc0.w + acc1.w) + (acc2.w + acc3.w);

        float4* p = (float4*)(part + (size_t)task * D);
        p[tid] = acc;

        __syncthreads();                     // all 256 part stores issued
        __threadfence();                     // publish part before flag
        if (tid == 0) {
            unsigned old = atomicAdd(&g_flag[task], 1u);
            if (t == 0) gen = old + 1u;      // this launch's generation
        }
    }

    // Combine phase: block b (<16) reduces row b's 64 partials into m[b].
    if (bid < B) {
        gen = __shfl_sync(0xFFFFFFFFu, gen, 0);  // broadcast within warp 0
        __shared__ unsigned s_gen;
        if (tid == 0) s_gen = gen;
        __syncthreads();
        gen = s_gen;

        // Wait for row bid's 64 task flags (threads 0..63 each watch one).
        if (tid < NCHUNK) {
            volatile unsigned* f = (volatile unsigned*)&g_flag[bid * NCHUNK + tid];
            while (*f < gen) __nanosleep(32);
        }
        __syncthreads();
        __threadfence();                     // acquire producers' part stores

        // m[bid][:] = (sum over 64 chunks of part[bid*64+c][:]) / S
        // 256 float4 per row over 256 threads -> 1 float4 each, 64 loads
        // (coalesced 4 KB per chunk step), 4-way unrolled accumulators.
        const float4* p4 = (const float4*)(part + (size_t)bid * NCHUNK * D);
        float4 a0 = make_float4(0.f, 0.f, 0.f, 0.f);
        float4 a1 = make_float4(0.f, 0.f, 0.f, 0.f);
        float4 a2 = make_float4(0.f, 0.f, 0.f, 0.f);
        float4 a3 = make_float4(0.f, 0.f, 0.f, 0.f);
        #pragma unroll 4
        for (int c = 0; c < NCHUNK; c += 4) {
            float4 v0 = p4[(size_t)(c + 0) * (D / 4) + tid];
            float4 v1 = p4[(size_t)(c + 1) * (D / 4) + tid];
            float4 v2 = p4[(size_t)(c + 2) * (D / 4) + tid];
            float4 v3 = p4[(size_t)(c + 3) * (D / 4) + tid];
            a0.x += v0.x; a0.y += v0.y; a0.z += v0.z; a0.w += v0.w;
            a1.x += v1.x; a1.y += v1.y; a1.z += v1.z; a1.w += v1.w;
            a2.x += v2.x; a2.y += v2.y; a2.z += v2.z; a2.w += v2.w;
            a3.x += v3.x; a3.y += v3.y; a3.z += v3.z; a3.w += v3.w;
        }
        const float inv = 1.0f / (float)S;
        float4 r;
        r.x = ((a0.x + a1.x) + (a2.x + a3.x)) * inv;
        r.y = ((a0.y + a1.y) + (a2.y + a3.y)) * inv;
        r.z = ((a0.z + a1.z) + (a2.z + a3.z)) * inv;
        r.w = ((a0.w + a1.w) + (a2.w + a3.w)) * inv;
        ((float4*)(m + (size_t)bid * D))[tid] = r;
    }
}

// ---------------------------------------------------------------------------
// K2/K3: split-K batched GEMV with smem-staged activations (R14-proven).
// KSPLIT=4: grid (128, 4) = 512 blocks, KCHUNK=256.
// PDL: W row LDGs (pure input) issue before the dependency sync.
__global__ void __launch_bounds__(256)
gemv_split_kernel(const float* __restrict__ vin,   // [B, D]
                  const float* __restrict__ W,     // [D, D]
                  float* __restrict__ vout) {      // [B, D] (+=)
    __shared__ float4 sh[B * (KCHUNK / 4)];   // 16 x 64 float4 = 16 KB

    const int K0 = blockIdx.y * KCHUNK;
    const int warp = threadIdx.x >> 5;
    const int lane = threadIdx.x & 31;
    const int n = blockIdx.x * 8 + warp;

    // Prologue: W row loads overlap the predecessor's tail + our ramp.
    const float4* Wr = (const float4*)(W + (size_t)n * D + K0);
    const float4 w0 = __ldg(&Wr[lane]);
    const float4 w1 = __ldg(&Wr[lane + 32]);

    cudaGridDependencySynchronize();   // vin/vout now valid

    // Cooperative fill: vin[:, K0:K0+256] -> 16 KB smem. 1024 float4 over
    // 256 threads = 4 per thread: 2 rows (warp, warp+8) x 2 column-halves.
    {
        const float4* v4 = (const float4*)vin;
        #pragma unroll
        for (int r = 0; r < 2; r++) {
            const int row = warp + r * 8;           // 0..15 over b
            sh[row * 64 + lane]      = v4[(size_t)row * (D / 4) + K0 / 4 + lane];
            sh[row * 64 + lane + 32] = v4[(size_t)row * (D / 4) + K0 / 4 + lane + 32];
        }
    }
    __syncthreads();

    float acc[B];
    #pragma unroll
    for (int b = 0; b < B; b++) {
        float4 v0 = sh[b * 64 + lane];
        float4 v1 = sh[b * 64 + lane + 32];
        acc[b] = ((w0.x * v0.x + w0.y * v0.y) + (w0.z * v0.z + w0.w * v0.w))
               + ((w1.x * v1.x + w1.y * v1.y) + (w1.z * v1.z + w1.w * v1.w));
    }

    // Interleaved pairwise reduction: 16 SHFLs; lane l ends with b = l & 15.
    float u8[8];
    #pragma unroll
    for (int j = 0; j < 8; j++) {
        float mine  = (lane & 1) ? acc[2 * j + 1] : acc[2 * j];
        float other = (lane & 1) ? acc[2 * j]     : acc[2 * j + 1];
        u8[j] = mine + __shfl_xor_sync(0xFFFFFFFFu, other, 1);
    }
    float u4[4];
    #pragma unroll
    for (int j = 0; j < 4; j++) {
        float mine  = (lane & 2) ? u8[2 * j + 1] : u8[2 * j];
        float other = (lane & 2) ? u8[2 * j]     : u8[2 * j + 1];
        u4[j] = mine + __shfl_xor_sync(0xFFFFFFFFu, other, 2);
    }
    float u2[2];
    #pragma unroll
    for (int j = 0; j < 2; j++) {
        float mine  = (lane & 4) ? u4[2 * j + 1] : u4[2 * j];
        float other = (lane & 4) ? u4[2 * j]     : u4[2 * j + 1];
        u2[j] = mine + __shfl_xor_sync(0xFFFFFFFFu, other, 4);
    }
    float mine  = (lane & 8) ? u2[1] : u2[0];
    float other = (lane & 8) ? u2[0] : u2[1];
    float u = mine + __shfl_xor_sync(0xFFFFFFFFu, other, 8);
    u += __shfl_xor_sync(0xFFFFFFFFu, u, 16);

    if (lane < B)
        atomicAdd(&vout[(size_t)lane * D + n], u);
}

// ---------------------------------------------------------------------------
extern "C" void kernel_launch(void* const* d_in, const int* in_sizes, int n_in,
                              void* d_out, int out_size) {
    const float* x     = (const float*)d_in[0];
    const float* W_enc = (const float*)d_in[1];
    const float* b_enc = (const float*)d_in[2];
    const float* W_out = (const float*)d_in[3];
    const float* b_out = (const float*)d_in[4];
    float* out = (float*)d_out;

    float* part; cudaGetSymbolAddress((void**)&part, g_part);
    float* m;    cudaGetSymbolAddress((void**)&m,    g_m);
    float* enc;  cudaGetSymbolAddress((void**)&enc,  g_enc);

    // K1: reduction + in-kernel combine (normal launch).
    reduce_combine_kernel<<<R_GRID, 256>>>(x, part, m, b_enc, enc, b_out, out);

    // GEMVs: PDL so each overlaps the predecessor's tail/ramp.
    cudaLaunchAttribute attr[1];
    attr[0].id = cudaLaunchAttributeProgrammaticStreamSerialization;
    attr[0].val.programmaticStreamSerializationAllowed = 1;

    {
        cudaLaunchConfig_t cfg = {};
        cfg.gridDim = dim3(D / 8, KSPLIT);
        cfg.blockDim = dim3(256);
        cfg.stream = 0;
        cfg.attrs = attr;
        cfg.numAttrs = 1;
        cudaLaunchKernelEx(&cfg, gemv_split_kernel,
                           (const float*)m, W_enc, enc);
    }
    {
        cudaLaunchConfig_t cfg = {};
        cfg.gridDim = dim3(D / 8, KSPLIT);
        cfg.blockDim = dim3(256);
        cfg.stream = 0;
        cfg.attrs = attr;
        cfg.numAttrs = 1;
        cudaLaunchKernelEx(&cfg, gemv_split_kernel,
                           (const float*)enc, W_out, out);
    }
}